// round 14
// baseline (speedup 1.0000x reference)
#include <cuda_runtime.h>
#include <cuda_fp16.h>
#include <cstdint>

// ---------------- problem constants ----------------
#define BATCHN  256
#define NTOK    196
#define DIMC    256
#define NHEAD   8
#define KDIM    32
#define VDIM    128
#define HPC     192            // per-head channels in h (q32 + k32 + v128)
#define HIDC    1536
#define DHC     1024
#define EPSV    1e-5f
#define SCALEV  0.17677669529663687f   // 32^{-1/2}
#define MROWS   (BATCHN * NTOK)        // 50176

// ---------------- scratch (device globals; no allocs allowed) ----------------
__device__ float g_Y[(size_t)MROWS * HIDC];     // h = x @ Wqkv^T   (308 MB)
__device__ float g_O[(size_t)MROWS * DHC];      // attention output (205 MB)
__device__ float g_bias[NHEAD * NTOK * NTOK];   // expanded bias (1.23 MB, L2-resident)
__device__ float g_psum[64 * HIDC];
__device__ float g_psq [64 * HIDC];
__device__ float g_A1[HIDC];
__device__ float g_B1[HIDC];
__device__ float g_A2[DIMC];
__device__ float g_B2[DIMC];

// ---------------- shared helpers ----------------
__device__ __forceinline__ void mma_f16(float& d0, float& d1, float& d2, float& d3,
                                        unsigned a0, unsigned a1, unsigned a2, unsigned a3,
                                        unsigned b0, unsigned b1)
{
    asm volatile(
        "mma.sync.aligned.m16n8k16.row.col.f32.f16.f16.f32 "
        "{%0,%1,%2,%3}, {%4,%5,%6,%7}, {%8,%9}, {%0,%1,%2,%3};"
        : "+f"(d0), "+f"(d1), "+f"(d2), "+f"(d3)
        : "r"(a0), "r"(a1), "r"(a2), "r"(a3), "r"(b0), "r"(b1));
}

__device__ __forceinline__ unsigned pack2(float lo, float hi)
{
    __half2 h = __floats2half2_rn(lo, hi);
    return *reinterpret_cast<unsigned*>(&h);
}

// ============================================================================
// FP16 tensor-core GEMM: C[M,N] = A[M,K] * B[N,K]^T  (row-major, K contiguous)
// ============================================================================

__device__ __forceinline__ int sw2(int k2, int x)
{
    return k2 * 136 + ((k2 >> 2) & 1) * 8 + x;
}

#define STG2_WORDS 1088

__global__ void __launch_bounds__(256, 2)
gemm_f16(const float* __restrict__ A, const float* __restrict__ B,
         float* __restrict__ C, int M, int N, int K)
{
    __shared__ unsigned smA[2][STG2_WORDS];
    __shared__ unsigned smB[2][STG2_WORDS];

    const int t    = threadIdx.x;
    const int lane = t & 31;
    const int w    = t >> 5;
    const int g    = lane >> 2;
    const int tig  = lane & 3;
    const int wM   = w >> 2;
    const int wN   = w & 3;
    const int m0   = blockIdx.y * 128;
    const int n0   = blockIdx.x * 128;

    const int r  = t >> 2;
    const int kc = (t & 3) * 4;
    const int k2c = kc >> 1;

    const float* pA0 = A + (size_t)(m0 + r)      * K + kc;
    const float* pA1 = A + (size_t)(m0 + r + 64) * K + kc;
    const float* pB0 = B + (size_t)(n0 + r)      * K + kc;
    const float* pB1 = B + (size_t)(n0 + r + 64) * K + kc;

    float acc[4][4][4] = {};
    const int T = K / 16;

    {
        float4 va0 = *(const float4*)pA0;
        float4 va1 = *(const float4*)pA1;
        float4 vb0 = *(const float4*)pB0;
        float4 vb1 = *(const float4*)pB1;
        smA[0][sw2(k2c,     r)]      = pack2(va0.x, va0.y);
        smA[0][sw2(k2c + 1, r)]      = pack2(va0.z, va0.w);
        smA[0][sw2(k2c,     r + 64)] = pack2(va1.x, va1.y);
        smA[0][sw2(k2c + 1, r + 64)] = pack2(va1.z, va1.w);
        smB[0][sw2(k2c,     r)]      = pack2(vb0.x, vb0.y);
        smB[0][sw2(k2c + 1, r)]      = pack2(vb0.z, vb0.w);
        smB[0][sw2(k2c,     r + 64)] = pack2(vb1.x, vb1.y);
        smB[0][sw2(k2c + 1, r + 64)] = pack2(vb1.z, vb1.w);
    }
    __syncthreads();

    int buf = 0;
    for (int it = 0; it < T; ++it) {
        float4 va0, va1, vb0, vb1;
        const bool more = (it + 1) < T;
        if (more) {
            const int ko = (it + 1) * 16;
            va0 = *(const float4*)(pA0 + ko);
            va1 = *(const float4*)(pA1 + ko);
            vb0 = *(const float4*)(pB0 + ko);
            vb1 = *(const float4*)(pB1 + ko);
        }

        const unsigned* sA = smA[buf];
        const unsigned* sB = smB[buf];

        {
            unsigned af[4][4];
            unsigned bfr[4][2];
#pragma unroll
            for (int ti = 0; ti < 4; ++ti) {
                const int m = wM * 64 + ti * 16 + g;
                af[ti][0] = sA[sw2(tig,     m)];
                af[ti][1] = sA[sw2(tig,     m + 8)];
                af[ti][2] = sA[sw2(tig + 4, m)];
                af[ti][3] = sA[sw2(tig + 4, m + 8)];
            }
#pragma unroll
            for (int tj = 0; tj < 4; ++tj) {
                const int n = wN * 32 + tj * 8 + g;
                bfr[tj][0] = sB[sw2(tig,     n)];
                bfr[tj][1] = sB[sw2(tig + 4, n)];
            }
#pragma unroll
            for (int ti = 0; ti < 4; ++ti)
#pragma unroll
                for (int tj = 0; tj < 4; ++tj)
                    mma_f16(acc[ti][tj][0], acc[ti][tj][1], acc[ti][tj][2], acc[ti][tj][3],
                            af[ti][0], af[ti][1], af[ti][2], af[ti][3],
                            bfr[tj][0], bfr[tj][1]);
        }

        if (more) {
            const int nb = buf ^ 1;
            smA[nb][sw2(k2c,     r)]      = pack2(va0.x, va0.y);
            smA[nb][sw2(k2c + 1, r)]      = pack2(va0.z, va0.w);
            smA[nb][sw2(k2c,     r + 64)] = pack2(va1.x, va1.y);
            smA[nb][sw2(k2c + 1, r + 64)] = pack2(va1.z, va1.w);
            smB[nb][sw2(k2c,     r)]      = pack2(vb0.x, vb0.y);
            smB[nb][sw2(k2c + 1, r)]      = pack2(vb0.z, vb0.w);
            smB[nb][sw2(k2c,     r + 64)] = pack2(vb1.x, vb1.y);
            smB[nb][sw2(k2c + 1, r + 64)] = pack2(vb1.z, vb1.w);
        }
        __syncthreads();
        buf ^= 1;
    }

#pragma unroll
    for (int ti = 0; ti < 4; ++ti) {
#pragma unroll
        for (int tj = 0; tj < 4; ++tj) {
            const int row = m0 + wM * 64 + ti * 16 + g;
            const int col = n0 + wN * 32 + tj * 8 + 2 * tig;
            float2 lo = {acc[ti][tj][0], acc[ti][tj][1]};
            float2 hi = {acc[ti][tj][2], acc[ti][tj][3]};
            *(float2*)&C[(size_t)row * N + col]       = lo;
            *(float2*)&C[(size_t)(row + 8) * N + col] = hi;
        }
    }
}

// ---------------- bias expansion: bias_full[h,i,j] = bias_table[h, idxs[i,j]] ----
__global__ void bias_expand(const float* __restrict__ bias_table,
                            const int*   __restrict__ idxs)
{
    const int i = blockIdx.x * 512 + threadIdx.x;
    if (i >= NHEAD * NTOK * NTOK) return;
    const int h  = i / (NTOK * NTOK);
    const int rc = i - h * NTOK * NTOK;
    g_bias[i] = bias_table[h * NTOK + idxs[rc]];
}

// ---------------- BN stats: deterministic two-stage reduction -------------------
__global__ void stats_partial(const float* __restrict__ X, int C)
{
    const int c  = blockIdx.x * 128 + threadIdx.x;
    const int r0 = blockIdx.y * 784;
    float s = 0.f, q = 0.f;
    const float* p = X + (size_t)r0 * C + c;
    for (int r = 0; r < 784; ++r) {
        float v = p[(size_t)r * C];
        s += v;
        q += v * v;
    }
    g_psum[blockIdx.y * C + c] = s;
    g_psq [blockIdx.y * C + c] = q;
}

__global__ void stats_finalize(const float* __restrict__ gam, const float* __restrict__ bet,
                               int C, int which)
{
    const int c = blockIdx.x * blockDim.x + threadIdx.x;
    if (c >= C) return;
    float s = 0.f, q = 0.f;
    for (int i = 0; i < 64; ++i) { s += g_psum[i * C + c]; q += g_psq[i * C + c]; }
    const float invM = 1.0f / (float)MROWS;
    const float mu   = s * invM;
    const float var  = q * invM - mu * mu;
    const float a    = gam[c] * rsqrtf(var + EPSV);
    const float bb   = bet[c] - mu * a;
    if (which == 0) { g_A1[c] = a; g_B1[c] = bb; }
    else            { g_A2[c] = a; g_B2[c] = bb; }
}

// ============================================================================
// Barrier-free tensor-core attention: one block per (batch, head), 256 threads
// (8 warps). Each warp owns full 16-row blocks end-to-end (QK -> softmax ->
// pack -> PV -> store) with warp-private scratch; NO block barriers after the
// cooperative QKV load.
// smem (u32 words):
//   uQ  [208][20]  fp16 q rows                       @ 0      (4160)
//   uK  [208][20]  fp16 k rows                       @ 4160   (4160)
//   uV  [128][108] fp16 V^T [channel][token]         @ 8320   (13824)
//   sA[192] sB[192]                                  @ 22144  (384)
//   Ssc 8 x [16][212] fp32 scores / fp16 P overlay   @ 22528  (27136)
// total 49664 u32 = 198656 B
// ============================================================================

#define AOFF_Q   0
#define AOFF_K   4160
#define AOFF_V   8320
#define AOFF_A   22144
#define AOFF_B   22336
#define AOFF_SC  22528
#define AOFF_TOT 49664

__device__ __forceinline__ float hswish(float x)
{
    return x * __saturatef((x + 3.0f) * (1.0f / 6.0f));
}

__global__ void __launch_bounds__(256, 1)
attn_kernel()
{
    extern __shared__ float sm[];
    unsigned* usm = reinterpret_cast<unsigned*>(sm);
    unsigned* uQ  = usm + AOFF_Q;
    unsigned* uK  = usm + AOFF_K;
    unsigned* uV  = usm + AOFF_V;
    float*    sA  = sm  + AOFF_A;
    float*    sB  = sm  + AOFF_B;

    const int b    = blockIdx.x;
    const int h    = blockIdx.y;
    const int tid  = threadIdx.x;            // 256
    const int w    = tid >> 5;               // 0..7
    const int lane = tid & 31;
    const int g    = lane >> 2;              // 0..7
    const int tig  = lane & 3;               // 0..3

    if (tid < HPC) { sA[tid] = g_A1[h * HPC + tid]; sB[tid] = g_B1[h * HPC + tid]; }

    // zero pads: Q/K rows 196..207, V token columns 196..215
    for (int i = tid; i < 12 * 20; i += 256) {
        const int rr = 196 + i / 20, cc = i % 20;
        uQ[rr * 20 + cc] = 0;
        uK[rr * 20 + cc] = 0;
    }
    for (int i = tid; i < 128 * 10; i += 256)
        uV[(i / 10) * 108 + 98 + (i % 10)] = 0;
    __syncthreads();

    // ---- cooperative load + BN-normalize + fp16 convert ----
    const size_t base = (size_t)(b * NTOK) * HIDC + h * HPC;
    for (int i = tid; i < NTOK * (HPC / 4); i += 256) {
        const int n  = i / (HPC / 4);
        const int c4 = (i - n * (HPC / 4)) * 4;
        float4 y = *(const float4*)&g_Y[base + (size_t)n * HIDC + c4];
        const float4 a  = *(const float4*)&sA[c4];
        const float4 bb = *(const float4*)&sB[c4];
        y.x = fmaf(y.x, a.x, bb.x);
        y.y = fmaf(y.y, a.y, bb.y);
        y.z = fmaf(y.z, a.z, bb.z);
        y.w = fmaf(y.w, a.w, bb.w);
        if (c4 < KDIM) {
            uQ[n * 20 + c4 / 2]     = pack2(y.x, y.y);
            uQ[n * 20 + c4 / 2 + 1] = pack2(y.z, y.w);
        } else if (c4 < 2 * KDIM) {
            const int cc = c4 - KDIM;
            uK[n * 20 + cc / 2]     = pack2(y.x, y.y);
            uK[n * 20 + cc / 2 + 1] = pack2(y.z, y.w);
        } else {
            const int ch = c4 - 2 * KDIM;
            __half* hv = reinterpret_cast<__half*>(uV);
            hv[(ch + 0) * 216 + n] = __float2half(y.x);
            hv[(ch + 1) * 216 + n] = __float2half(y.y);
            hv[(ch + 2) * 216 + n] = __float2half(y.z);
            hv[(ch + 3) * 216 + n] = __float2half(y.w);
        }
    }
    __syncthreads();   // the ONLY block barrier: K/V shared across warps

    float* Sw  = sm + AOFF_SC + w * 3392;            // warp-private [16][212] fp32
    unsigned* uPw = reinterpret_cast<unsigned*>(Sw); // fp16 P overlay (in place)
    const float* biasH = g_bias + (size_t)h * NTOK * NTOK;

    // 13 row-blocks of 16 over 8 warps: warp w handles blocks w and w+8
    for (int blk = w; blk < 13; blk += 8) {
        const int R = blk * 16;                      // global base row

        // ---- QK^T + scale + bias -> Sw (fp32) ----
        {
            const int rowg = R + g;
            const unsigned aq0 = uQ[rowg * 20 + tig];
            const unsigned aq1 = uQ[(rowg + 8) * 20 + tig];
            const unsigned aq2 = uQ[rowg * 20 + tig + 4];
            const unsigned aq3 = uQ[(rowg + 8) * 20 + tig + 4];
            const unsigned aq4 = uQ[rowg * 20 + 8 + tig];
            const unsigned aq5 = uQ[(rowg + 8) * 20 + 8 + tig];
            const unsigned aq6 = uQ[rowg * 20 + 8 + tig + 4];
            const unsigned aq7 = uQ[(rowg + 8) * 20 + 8 + tig + 4];

            const bool okA = (R + g)     < NTOK;
            const bool okB = (R + g + 8) < NTOK;
            const float* bRA = biasH + (size_t)(R + g) * NTOK;
            const float* bRB = biasH + (size_t)(R + g + 8) * NTOK;

#pragma unroll
            for (int j = 0; j < 26; ++j) {
                const int tok = 8 * j + g;
                const unsigned b00 = uK[tok * 20 + tig];
                const unsigned b01 = uK[tok * 20 + tig + 4];
                const unsigned b10 = uK[tok * 20 + 8 + tig];
                const unsigned b11 = uK[tok * 20 + 8 + tig + 4];
                float c0 = 0.f, c1 = 0.f, c2 = 0.f, c3 = 0.f;
                mma_f16(c0, c1, c2, c3, aq0, aq1, aq2, aq3, b00, b01);
                mma_f16(c0, c1, c2, c3, aq4, aq5, aq6, aq7, b10, b11);
                const int col0 = 8 * j + 2 * tig;
                if (col0 < NTOK) {            // NTOK even -> col0+1 also valid
                    if (okA) {
                        const float2 bv = *(const float2*)&bRA[col0];
                        float2 sv = {fmaf(c0, SCALEV, bv.x), fmaf(c1, SCALEV, bv.y)};
                        *(float2*)&Sw[g * 212 + col0] = sv;
                    }
                    if (okB) {
                        const float2 bv = *(const float2*)&bRB[col0];
                        float2 sv = {fmaf(c2, SCALEV, bv.x), fmaf(c3, SCALEV, bv.y)};
                        *(float2*)&Sw[(g + 8) * 212 + col0] = sv;
                    }
                }
            }
        }
        __syncwarp();

        // ---- warp-local softmax + in-place fp16 pack ----
        for (int rl = 0; rl < 16; ++rl) {
            if (R + rl >= NTOK) break;
            float* Sp = Sw + rl * 212;
            float m = -1e30f;
            for (int j = lane; j < NTOK; j += 32) m = fmaxf(m, Sp[j]);
#pragma unroll
            for (int o = 16; o; o >>= 1) m = fmaxf(m, __shfl_xor_sync(0xffffffffu, m, o));
            float sum = 0.f;
            for (int j = lane; j < NTOK; j += 32) {
                const float e = __expf(Sp[j] - m);
                Sp[j] = e;
                sum += e;
            }
#pragma unroll
            for (int o = 16; o; o >>= 1) sum += __shfl_xor_sync(0xffffffffu, sum, o);
            const float inv = 1.0f / sum;
            // in-place 2:1 compaction fp32 -> packed fp16 (safe: chunk t reads
            // words 64t..64t+63, then writes 32t..32t+31 after syncwarp)
            unsigned* uPr = reinterpret_cast<unsigned*>(Sp);
#pragma unroll
            for (int t = 0; t < 4; ++t) {
                const int jj = 32 * t + lane;
                float f0 = 0.f, f1 = 0.f;
                if (jj < 104) {
                    const int ca = 2 * jj, cb = ca + 1;
                    f0 = (ca < NTOK) ? Sp[ca] * inv : 0.f;
                    f1 = (cb < NTOK) ? Sp[cb] * inv : 0.f;
                }
                __syncwarp();
                if (jj < 104) uPr[jj] = pack2(f0, f1);
                __syncwarp();
            }
        }
        __syncwarp();

        // ---- PV (fp16 mma) over all 128 channels + hswish -> g_O ----
        {
            float acc[16][4];
#pragma unroll
            for (int nj = 0; nj < 16; ++nj)
#pragma unroll
                for (int q = 0; q < 4; ++q) acc[nj][q] = 0.f;

#pragma unroll
            for (int ks = 0; ks < 13; ++ks) {
                const int ko = 8 * ks;
                const unsigned pa0 = uPw[g * 212 + ko + tig];
                const unsigned pa1 = uPw[(g + 8) * 212 + ko + tig];
                const unsigned pa2 = uPw[g * 212 + ko + tig + 4];
                const unsigned pa3 = uPw[(g + 8) * 212 + ko + tig + 4];
#pragma unroll
                for (int nj = 0; nj < 16; ++nj) {
                    const int ch = 8 * nj + g;
                    const unsigned vb0 = uV[ch * 108 + ko + tig];
                    const unsigned vb1 = uV[ch * 108 + ko + tig + 4];
                    mma_f16(acc[nj][0], acc[nj][1], acc[nj][2], acc[nj][3],
                            pa0, pa1, pa2, pa3, vb0, vb1);
                }
            }

            const int rA = R + g, rB = R + g + 8;
#pragma unroll
            for (int nj = 0; nj < 16; ++nj) {
                const int col = h * VDIM + 8 * nj + 2 * tig;
                if (rA < NTOK) {
                    float2 v = {hswish(acc[nj][0]), hswish(acc[nj][1])};
                    *(float2*)&g_O[(size_t)(b * NTOK + rA) * DHC + col] = v;
                }
                if (rB < NTOK) {
                    float2 v = {hswish(acc[nj][2]), hswish(acc[nj][3])};
                    *(float2*)&g_O[(size_t)(b * NTOK + rB) * DHC + col] = v;
                }
            }
        }
        __syncwarp();
    }
}

// ---------------- final BN apply (in place on d_out) ----------------------------
__global__ void norm2_kernel(float* __restrict__ Z)
{
    const size_t i = (size_t)blockIdx.x * 256 + threadIdx.x;
    float4 z = ((float4*)Z)[i];
    const int c4 = (int)(i & (DIMC / 4 - 1));
    const float4 a  = ((const float4*)g_A2)[c4];
    const float4 bb = ((const float4*)g_B2)[c4];
    z.x = fmaf(z.x, a.x, bb.x);
    z.y = fmaf(z.y, a.y, bb.y);
    z.z = fmaf(z.z, a.z, bb.z);
    z.w = fmaf(z.w, a.w, bb.w);
    ((float4*)Z)[i] = z;
}

// ---------------- launch ---------------------------------------------------------
extern "C" void kernel_launch(void* const* d_in, const int* in_sizes, int n_in,
                              void* d_out, int out_size)
{
    const float* x          = (const float*)d_in[0];
    const float* Wqkv       = (const float*)d_in[1];
    const float* g1         = (const float*)d_in[2];
    const float* b1         = (const float*)d_in[3];
    const float* bias_table = (const float*)d_in[4];
    const float* Wproj      = (const float*)d_in[5];
    const float* g2         = (const float*)d_in[6];
    const float* b2         = (const float*)d_in[7];
    const int*   idxs       = (const int*)d_in[8];
    float*       out        = (float*)d_out;

    float *Y, *O;
    cudaGetSymbolAddress((void**)&Y, g_Y);
    cudaGetSymbolAddress((void**)&O, g_O);

    const size_t attn_smem = (size_t)AOFF_TOT * sizeof(unsigned);
    cudaFuncSetAttribute(attn_kernel, cudaFuncAttributeMaxDynamicSharedMemorySize,
                         (int)attn_smem);

    // 0) expand relative-position bias to full [H,N,N] (L2-resident)
    bias_expand<<<(NHEAD * NTOK * NTOK + 511) / 512, 512>>>(bias_table, idxs);
    // 1) h = x @ Wqkv^T  (fp16 tensor cores, fp32 accum)
    gemm_f16<<<dim3(HIDC / 128, MROWS / 128), 256>>>(x, Wqkv, Y, MROWS, HIDC, DIMC);
    // 2) BN1 stats -> affine
    stats_partial<<<dim3(HIDC / 128, 64), 128>>>(Y, HIDC);
    stats_finalize<<<6, 256>>>(g1, b1, HIDC, 0);
    // 3) attention + hardswish (fp16 tensor cores, barrier-free warps)
    attn_kernel<<<dim3(BATCHN, NHEAD), 256, attn_smem>>>();
    // 4) Z = o @ Wproj^T  (fp16 tensor cores, into d_out)
    gemm_f16<<<dim3(DIMC / 128, MROWS / 128), 256>>>(O, Wproj, out, MROWS, DIMC, DHC);
    // 5) BN2 stats -> affine
    stats_partial<<<dim3(DIMC / 128, 64), 128>>>(out, DIMC);
    stats_finalize<<<1, 256>>>(g2, b2, DIMC, 1);
    // 6) apply BN2 in place
    norm2_kernel<<<(MROWS * DIMC / 4) / 256, 256>>>(out);
}

// round 16
// speedup vs baseline: 1.4551x; 1.4551x over previous
#include <cuda_runtime.h>
#include <cuda_fp16.h>
#include <cstdint>

// ---------------- problem constants ----------------
#define BATCHN  256
#define NTOK    196
#define DIMC    256
#define NHEAD   8
#define KDIM    32
#define VDIM    128
#define HPC     192            // per-head channels in h (q32 + k32 + v128)
#define HIDC    1536
#define DHC     1024
#define EPSV    1e-5f
#define SCALEV  0.17677669529663687f   // 32^{-1/2}
#define MROWS   (BATCHN * NTOK)        // 50176

// ---------------- scratch (device globals; no allocs allowed) ----------------
__device__ float g_Y[(size_t)MROWS * HIDC];     // h = x @ Wqkv^T   (308 MB)
__device__ float g_O[(size_t)MROWS * DHC];      // attention output (205 MB)
__device__ float g_bias[NHEAD * NTOK * NTOK];   // expanded bias (1.23 MB, L2-resident)
__device__ float g_psum[64 * HIDC];
__device__ float g_psq [64 * HIDC];
__device__ float g_A1[HIDC];
__device__ float g_B1[HIDC];
__device__ float g_A2[DIMC];
__device__ float g_B2[DIMC];

// ---------------- shared helpers ----------------
__device__ __forceinline__ void mma_f16(float& d0, float& d1, float& d2, float& d3,
                                        unsigned a0, unsigned a1, unsigned a2, unsigned a3,
                                        unsigned b0, unsigned b1)
{
    asm volatile(
        "mma.sync.aligned.m16n8k16.row.col.f32.f16.f16.f32 "
        "{%0,%1,%2,%3}, {%4,%5,%6,%7}, {%8,%9}, {%0,%1,%2,%3};"
        : "+f"(d0), "+f"(d1), "+f"(d2), "+f"(d3)
        : "r"(a0), "r"(a1), "r"(a2), "r"(a3), "r"(b0), "r"(b1));
}

__device__ __forceinline__ unsigned pack2(float lo, float hi)
{
    __half2 h = __floats2half2_rn(lo, hi);
    return *reinterpret_cast<unsigned*>(&h);
}

// ============================================================================
// FP16 tensor-core GEMM: C[M,N] = A[M,K] * B[N,K]^T  (row-major, K contiguous)
// ============================================================================

__device__ __forceinline__ int sw2(int k2, int x)
{
    return k2 * 136 + ((k2 >> 2) & 1) * 8 + x;
}

#define STG2_WORDS 1088

__global__ void __launch_bounds__(256, 2)
gemm_f16(const float* __restrict__ A, const float* __restrict__ B,
         float* __restrict__ C, int M, int N, int K)
{
    __shared__ unsigned smA[2][STG2_WORDS];
    __shared__ unsigned smB[2][STG2_WORDS];

    const int t    = threadIdx.x;
    const int lane = t & 31;
    const int w    = t >> 5;
    const int g    = lane >> 2;
    const int tig  = lane & 3;
    const int wM   = w >> 2;
    const int wN   = w & 3;
    const int m0   = blockIdx.y * 128;
    const int n0   = blockIdx.x * 128;

    const int r  = t >> 2;
    const int kc = (t & 3) * 4;
    const int k2c = kc >> 1;

    const float* pA0 = A + (size_t)(m0 + r)      * K + kc;
    const float* pA1 = A + (size_t)(m0 + r + 64) * K + kc;
    const float* pB0 = B + (size_t)(n0 + r)      * K + kc;
    const float* pB1 = B + (size_t)(n0 + r + 64) * K + kc;

    float acc[4][4][4] = {};
    const int T = K / 16;

    {
        float4 va0 = *(const float4*)pA0;
        float4 va1 = *(const float4*)pA1;
        float4 vb0 = *(const float4*)pB0;
        float4 vb1 = *(const float4*)pB1;
        smA[0][sw2(k2c,     r)]      = pack2(va0.x, va0.y);
        smA[0][sw2(k2c + 1, r)]      = pack2(va0.z, va0.w);
        smA[0][sw2(k2c,     r + 64)] = pack2(va1.x, va1.y);
        smA[0][sw2(k2c + 1, r + 64)] = pack2(va1.z, va1.w);
        smB[0][sw2(k2c,     r)]      = pack2(vb0.x, vb0.y);
        smB[0][sw2(k2c + 1, r)]      = pack2(vb0.z, vb0.w);
        smB[0][sw2(k2c,     r + 64)] = pack2(vb1.x, vb1.y);
        smB[0][sw2(k2c + 1, r + 64)] = pack2(vb1.z, vb1.w);
    }
    __syncthreads();

    int buf = 0;
    for (int it = 0; it < T; ++it) {
        float4 va0, va1, vb0, vb1;
        const bool more = (it + 1) < T;
        if (more) {
            const int ko = (it + 1) * 16;
            va0 = *(const float4*)(pA0 + ko);
            va1 = *(const float4*)(pA1 + ko);
            vb0 = *(const float4*)(pB0 + ko);
            vb1 = *(const float4*)(pB1 + ko);
        }

        const unsigned* sA = smA[buf];
        const unsigned* sB = smB[buf];

        {
            unsigned af[4][4];
            unsigned bfr[4][2];
#pragma unroll
            for (int ti = 0; ti < 4; ++ti) {
                const int m = wM * 64 + ti * 16 + g;
                af[ti][0] = sA[sw2(tig,     m)];
                af[ti][1] = sA[sw2(tig,     m + 8)];
                af[ti][2] = sA[sw2(tig + 4, m)];
                af[ti][3] = sA[sw2(tig + 4, m + 8)];
            }
#pragma unroll
            for (int tj = 0; tj < 4; ++tj) {
                const int n = wN * 32 + tj * 8 + g;
                bfr[tj][0] = sB[sw2(tig,     n)];
                bfr[tj][1] = sB[sw2(tig + 4, n)];
            }
#pragma unroll
            for (int ti = 0; ti < 4; ++ti)
#pragma unroll
                for (int tj = 0; tj < 4; ++tj)
                    mma_f16(acc[ti][tj][0], acc[ti][tj][1], acc[ti][tj][2], acc[ti][tj][3],
                            af[ti][0], af[ti][1], af[ti][2], af[ti][3],
                            bfr[tj][0], bfr[tj][1]);
        }

        if (more) {
            const int nb = buf ^ 1;
            smA[nb][sw2(k2c,     r)]      = pack2(va0.x, va0.y);
            smA[nb][sw2(k2c + 1, r)]      = pack2(va0.z, va0.w);
            smA[nb][sw2(k2c,     r + 64)] = pack2(va1.x, va1.y);
            smA[nb][sw2(k2c + 1, r + 64)] = pack2(va1.z, va1.w);
            smB[nb][sw2(k2c,     r)]      = pack2(vb0.x, vb0.y);
            smB[nb][sw2(k2c + 1, r)]      = pack2(vb0.z, vb0.w);
            smB[nb][sw2(k2c,     r + 64)] = pack2(vb1.x, vb1.y);
            smB[nb][sw2(k2c + 1, r + 64)] = pack2(vb1.z, vb1.w);
        }
        __syncthreads();
        buf ^= 1;
    }

#pragma unroll
    for (int ti = 0; ti < 4; ++ti) {
#pragma unroll
        for (int tj = 0; tj < 4; ++tj) {
            const int row = m0 + wM * 64 + ti * 16 + g;
            const int col = n0 + wN * 32 + tj * 8 + 2 * tig;
            float2 lo = {acc[ti][tj][0], acc[ti][tj][1]};
            float2 hi = {acc[ti][tj][2], acc[ti][tj][3]};
            *(float2*)&C[(size_t)row * N + col]       = lo;
            *(float2*)&C[(size_t)(row + 8) * N + col] = hi;
        }
    }
}

// ---------------- bias expansion: bias_full[h,i,j] = bias_table[h, idxs[i,j]] ----
__global__ void bias_expand(const float* __restrict__ bias_table,
                            const int*   __restrict__ idxs)
{
    const int i = blockIdx.x * 512 + threadIdx.x;
    if (i >= NHEAD * NTOK * NTOK) return;
    const int h  = i / (NTOK * NTOK);
    const int rc = i - h * NTOK * NTOK;
    g_bias[i] = bias_table[h * NTOK + idxs[rc]];
}

// ---------------- BN stats: deterministic two-stage reduction -------------------
__global__ void stats_partial(const float* __restrict__ X, int C)
{
    const int c  = blockIdx.x * 128 + threadIdx.x;
    const int r0 = blockIdx.y * 784;
    float s = 0.f, q = 0.f;
    const float* p = X + (size_t)r0 * C + c;
    for (int r = 0; r < 784; ++r) {
        float v = p[(size_t)r * C];
        s += v;
        q += v * v;
    }
    g_psum[blockIdx.y * C + c] = s;
    g_psq [blockIdx.y * C + c] = q;
}

__global__ void stats_finalize(const float* __restrict__ gam, const float* __restrict__ bet,
                               int C, int which)
{
    const int c = blockIdx.x * blockDim.x + threadIdx.x;
    if (c >= C) return;
    float s = 0.f, q = 0.f;
    for (int i = 0; i < 64; ++i) { s += g_psum[i * C + c]; q += g_psq[i * C + c]; }
    const float invM = 1.0f / (float)MROWS;
    const float mu   = s * invM;
    const float var  = q * invM - mu * mu;
    const float a    = gam[c] * rsqrtf(var + EPSV);
    const float bb   = bet[c] - mu * a;
    if (which == 0) { g_A1[c] = a; g_B1[c] = bb; }
    else            { g_A2[c] = a; g_B2[c] = bb; }
}

// ============================================================================
// Tensor-core attention: one block per (batch, head); 512 threads, 16 warps.
// smem (u32 words):
//   Qh  [208][20]  fp16 q rows (stride 40 halves)          @ 0      (4160)
//   Kh  [208][20]  fp16 k rows                             @ 4160   (4160)
//   VhT [128][108] fp16 V transposed [channel][token]      @ 8320   (13824)
//   S   [64][212]  fp32 scores                             @ 22144  (13568)
//   Ph  [64][108]  fp16 UNNORMALIZED probs (exp(s-m))      @ 35712  (6912)
//   sA[192] sB[192] sInv[64]                               @ 42624..
// total 43072 u32 = 172288 B
// ============================================================================

#define AOFF_Q   0
#define AOFF_K   4160
#define AOFF_V   8320
#define AOFF_S   22144
#define AOFF_P   35712
#define AOFF_A   42624
#define AOFF_B   42816
#define AOFF_INV 43008
#define AOFF_TOT 43072

__device__ __forceinline__ float hswish(float x)
{
    return x * __saturatef((x + 3.0f) * (1.0f / 6.0f));
}

__global__ void __launch_bounds__(512, 1)
attn_kernel()
{
    extern __shared__ float sm[];
    unsigned* usm  = reinterpret_cast<unsigned*>(sm);
    unsigned* uQ   = usm + AOFF_Q;
    unsigned* uK   = usm + AOFF_K;
    unsigned* uV   = usm + AOFF_V;
    float*    S    = sm  + AOFF_S;
    unsigned* uP   = usm + AOFF_P;
    float*    sA   = sm  + AOFF_A;
    float*    sB   = sm  + AOFF_B;
    float*    sInv = sm  + AOFF_INV;

    const int b    = blockIdx.x;
    const int h    = blockIdx.y;
    const int tid  = threadIdx.x;            // 512
    const int w    = tid >> 5;               // 0..15
    const int lane = tid & 31;
    const int g    = lane >> 2;              // 0..7
    const int tig  = lane & 3;               // 0..3

    if (tid < HPC) { sA[tid] = g_A1[h * HPC + tid]; sB[tid] = g_B1[h * HPC + tid]; }

    // zero pads: Q/K rows 196..207, V token columns 196..215, P pad cols 98..107
    for (int i = tid; i < 12 * 20; i += 512) {
        const int rr = 196 + i / 20, cc = i % 20;
        uQ[rr * 20 + cc] = 0;
        uK[rr * 20 + cc] = 0;
    }
    for (int i = tid; i < 128 * 10; i += 512)
        uV[(i / 10) * 108 + 98 + (i % 10)] = 0;
    for (int i = tid; i < 64 * 10; i += 512)
        uP[(i / 10) * 108 + 98 + (i % 10)] = 0;
    __syncthreads();

    // ---- load + BN-normalize + fp16 convert ----
    const size_t base = (size_t)(b * NTOK) * HIDC + h * HPC;
    for (int i = tid; i < NTOK * (HPC / 4); i += 512) {
        const int n  = i / (HPC / 4);
        const int c4 = (i - n * (HPC / 4)) * 4;
        float4 y = *(const float4*)&g_Y[base + (size_t)n * HIDC + c4];
        const float4 a  = *(const float4*)&sA[c4];
        const float4 bb = *(const float4*)&sB[c4];
        y.x = fmaf(y.x, a.x, bb.x);
        y.y = fmaf(y.y, a.y, bb.y);
        y.z = fmaf(y.z, a.z, bb.z);
        y.w = fmaf(y.w, a.w, bb.w);
        if (c4 < KDIM) {
            uQ[n * 20 + c4 / 2]     = pack2(y.x, y.y);
            uQ[n * 20 + c4 / 2 + 1] = pack2(y.z, y.w);
        } else if (c4 < 2 * KDIM) {
            const int cc = c4 - KDIM;
            uK[n * 20 + cc / 2]     = pack2(y.x, y.y);
            uK[n * 20 + cc / 2 + 1] = pack2(y.z, y.w);
        } else {
            const int ch = c4 - 2 * KDIM;
            __half* hv = reinterpret_cast<__half*>(uV);
            hv[(ch + 0) * 216 + n] = __float2half(y.x);
            hv[(ch + 1) * 216 + n] = __float2half(y.y);
            hv[(ch + 2) * 216 + n] = __float2half(y.z);
            hv[(ch + 3) * 216 + n] = __float2half(y.w);
        }
    }
    __syncthreads();

    const int rb = w >> 2;           // 0..3: 16-row block within 64-row tile
    const int ws = w & 3;            // 0..3: work split within phase
    const int r0 = rb * 16;

    const float* biasH = g_bias + (size_t)h * NTOK * NTOK;

    for (int tbase = 0; tbase < NTOK; tbase += 64) {
        const int tcount = (NTOK - tbase < 64) ? (NTOK - tbase) : 64;

        // ---- QK^T + scale + bias -> S (fp32) ----
        if (r0 < tcount) {
            const int rowg = tbase + r0 + g;
            unsigned aq0 = uQ[rowg * 20 + tig];
            unsigned aq1 = uQ[(rowg + 8) * 20 + tig];
            unsigned aq2 = uQ[rowg * 20 + tig + 4];
            unsigned aq3 = uQ[(rowg + 8) * 20 + tig + 4];
            unsigned aq4 = uQ[rowg * 20 + 8 + tig];
            unsigned aq5 = uQ[(rowg + 8) * 20 + 8 + tig];
            unsigned aq6 = uQ[rowg * 20 + 8 + tig + 4];
            unsigned aq7 = uQ[(rowg + 8) * 20 + 8 + tig + 4];

            const int rA = r0 + g, rB = r0 + g + 8;
            const float* bRA = biasH + (size_t)(tbase + rA) * NTOK;
            const float* bRB = biasH + (size_t)(tbase + rB) * NTOK;
            for (int j = ws; j < 26; j += 4) {
                const int tok = 8 * j + g;
                const unsigned b00 = uK[tok * 20 + tig];
                const unsigned b01 = uK[tok * 20 + tig + 4];
                const unsigned b10 = uK[tok * 20 + 8 + tig];
                const unsigned b11 = uK[tok * 20 + 8 + tig + 4];
                float c0 = 0.f, c1 = 0.f, c2 = 0.f, c3 = 0.f;
                mma_f16(c0, c1, c2, c3, aq0, aq1, aq2, aq3, b00, b01);
                mma_f16(c0, c1, c2, c3, aq4, aq5, aq6, aq7, b10, b11);
                const int col0 = 8 * j + 2 * tig;
                if (col0 < NTOK) {   // NTOK even -> col0 < NTOK implies col0+1 < NTOK
                    if (rA < tcount) {
                        const float2 bv = *(const float2*)&bRA[col0];
                        float2 sv = {fmaf(c0, SCALEV, bv.x), fmaf(c1, SCALEV, bv.y)};
                        *(float2*)&S[rA * 212 + col0] = sv;
                    }
                    if (rB < tcount) {
                        const float2 bv = *(const float2*)&bRB[col0];
                        float2 sv = {fmaf(c2, SCALEV, bv.x), fmaf(c3, SCALEV, bv.y)};
                        *(float2*)&S[rB * 212 + col0] = sv;
                    }
                }
            }
        }
        __syncthreads();

        // ---- softmax rows: 2 vectorized passes; P holds UNNORMALIZED exp ----
        // 196 = 49 float4 exactly; pads never touched.
        for (int rl = w; rl < tcount; rl += 16) {
            const float4* Sp4 = (const float4*)(S + rl * 212);
            float m = -1e30f;
            for (int j4 = lane; j4 < 49; j4 += 32) {
                const float4 v = Sp4[j4];
                m = fmaxf(m, fmaxf(fmaxf(v.x, v.y), fmaxf(v.z, v.w)));
            }
#pragma unroll
            for (int o = 16; o; o >>= 1) m = fmaxf(m, __shfl_xor_sync(0xffffffffu, m, o));
            float sum = 0.f;
            for (int j4 = lane; j4 < 49; j4 += 32) {
                const float4 v = Sp4[j4];
                const float e0 = __expf(v.x - m);
                const float e1 = __expf(v.y - m);
                const float e2 = __expf(v.z - m);
                const float e3 = __expf(v.w - m);
                sum += (e0 + e1) + (e2 + e3);
                uint2 pk = {pack2(e0, e1), pack2(e2, e3)};
                *(uint2*)&uP[rl * 108 + 2 * j4] = pk;
            }
#pragma unroll
            for (int o = 16; o; o >>= 1) sum += __shfl_xor_sync(0xffffffffu, sum, o);
            if (lane == 0) sInv[rl] = 1.0f / sum;
        }
        __syncthreads();

        // ---- PV (fp16 mma) + deferred normalization + hswish -> g_O ----
        if (r0 < tcount) {
            float acc[4][4] = {};
#pragma unroll
            for (int ks = 0; ks < 13; ++ks) {
                const int ko = 8 * ks;
                const unsigned pa0 = uP[(r0 + g) * 108 + ko + tig];
                const unsigned pa1 = uP[(r0 + g + 8) * 108 + ko + tig];
                const unsigned pa2 = uP[(r0 + g) * 108 + ko + tig + 4];
                const unsigned pa3 = uP[(r0 + g + 8) * 108 + ko + tig + 4];
#pragma unroll
                for (int nj = 0; nj < 4; ++nj) {
                    const int ch = ws * 32 + 8 * nj + g;
                    const unsigned vb0 = uV[ch * 108 + ko + tig];
                    const unsigned vb1 = uV[ch * 108 + ko + tig + 4];
                    mma_f16(acc[nj][0], acc[nj][1], acc[nj][2], acc[nj][3],
                            pa0, pa1, pa2, pa3, vb0, vb1);
                }
            }
            const int rA = r0 + g, rB = r0 + g + 8;
            const float invA = (rA < tcount) ? sInv[rA] : 0.f;
            const float invB = (rB < tcount) ? sInv[rB] : 0.f;
#pragma unroll
            for (int nj = 0; nj < 4; ++nj) {
                const int col = h * VDIM + ws * 32 + 8 * nj + 2 * tig;
                if (rA < tcount) {
                    float2 v = {hswish(acc[nj][0] * invA), hswish(acc[nj][1] * invA)};
                    *(float2*)&g_O[(size_t)(b * NTOK + tbase + rA) * DHC + col] = v;
                }
                if (rB < tcount) {
                    float2 v = {hswish(acc[nj][2] * invB), hswish(acc[nj][3] * invB)};
                    *(float2*)&g_O[(size_t)(b * NTOK + tbase + rB) * DHC + col] = v;
                }
            }
        }
        __syncthreads();
    }
}

// ---------------- final BN apply (in place on d_out) ----------------------------
__global__ void norm2_kernel(float* __restrict__ Z)
{
    const size_t i = (size_t)blockIdx.x * 256 + threadIdx.x;
    float4 z = ((float4*)Z)[i];
    const int c4 = (int)(i & (DIMC / 4 - 1));
    const float4 a  = ((const float4*)g_A2)[c4];
    const float4 bb = ((const float4*)g_B2)[c4];
    z.x = fmaf(z.x, a.x, bb.x);
    z.y = fmaf(z.y, a.y, bb.y);
    z.z = fmaf(z.z, a.z, bb.z);
    z.w = fmaf(z.w, a.w, bb.w);
    ((float4*)Z)[i] = z;
}

// ---------------- launch ---------------------------------------------------------
extern "C" void kernel_launch(void* const* d_in, const int* in_sizes, int n_in,
                              void* d_out, int out_size)
{
    const float* x          = (const float*)d_in[0];
    const float* Wqkv       = (const float*)d_in[1];
    const float* g1         = (const float*)d_in[2];
    const float* b1         = (const float*)d_in[3];
    const float* bias_table = (const float*)d_in[4];
    const float* Wproj      = (const float*)d_in[5];
    const float* g2         = (const float*)d_in[6];
    const float* b2         = (const float*)d_in[7];
    const int*   idxs       = (const int*)d_in[8];
    float*       out        = (float*)d_out;

    float *Y, *O;
    cudaGetSymbolAddress((void**)&Y, g_Y);
    cudaGetSymbolAddress((void**)&O, g_O);

    const size_t attn_smem = (size_t)AOFF_TOT * sizeof(float);
    cudaFuncSetAttribute(attn_kernel, cudaFuncAttributeMaxDynamicSharedMemorySize,
                         (int)attn_smem);

    // 0) expand relative-position bias to full [H,N,N] (L2-resident)
    bias_expand<<<(NHEAD * NTOK * NTOK + 511) / 512, 512>>>(bias_table, idxs);
    // 1) h = x @ Wqkv^T  (fp16 tensor cores, fp32 accum)
    gemm_f16<<<dim3(HIDC / 128, MROWS / 128), 256>>>(x, Wqkv, Y, MROWS, HIDC, DIMC);
    // 2) BN1 stats -> affine
    stats_partial<<<dim3(HIDC / 128, 64), 128>>>(Y, HIDC);
    stats_finalize<<<6, 256>>>(g1, b1, HIDC, 0);
    // 3) attention + hardswish (fp16 tensor cores)
    attn_kernel<<<dim3(BATCHN, NHEAD), 512, attn_smem>>>();
    // 4) Z = o @ Wproj^T  (fp16 tensor cores, into d_out)
    gemm_f16<<<dim3(DIMC / 128, MROWS / 128), 256>>>(O, Wproj, out, MROWS, DIMC, DHC);
    // 5) BN2 stats -> affine
    stats_partial<<<dim3(DIMC / 128, 64), 128>>>(out, DIMC);
    stats_finalize<<<1, 256>>>(g2, b2, DIMC, 1);
    // 6) apply BN2 in place
    norm2_kernel<<<(MROWS * DIMC / 4) / 256, 256>>>(out);
}

// round 17
// speedup vs baseline: 1.4810x; 1.0178x over previous
#include <cuda_runtime.h>
#include <cuda_fp16.h>
#include <cstdint>

// ---------------- problem constants ----------------
#define BATCHN  256
#define NTOK    196
#define DIMC    256
#define NHEAD   8
#define KDIM    32
#define VDIM    128
#define HPC     192            // per-head channels in h (q32 + k32 + v128)
#define HIDC    1536
#define DHC     1024
#define EPSV    1e-5f
#define SCALEV  0.17677669529663687f   // 32^{-1/2}
#define MROWS   (BATCHN * NTOK)        // 50176

// ---------------- scratch (device globals; no allocs allowed) ----------------
__device__ __half g_Yh[(size_t)MROWS * HIDC];   // h = x @ Wqkv^T   (154 MB, fp16)
__device__ __half g_Oh[(size_t)MROWS * DHC];    // attention output (103 MB, fp16)
__device__ float  g_bias[NHEAD * NTOK * NTOK];  // expanded bias (1.23 MB, L2-resident)
__device__ float  g_psum[64 * HIDC];
__device__ float  g_psq [64 * HIDC];
__device__ float  g_A1[HIDC];
__device__ float  g_B1[HIDC];
__device__ float  g_A2[DIMC];
__device__ float  g_B2[DIMC];

// ---------------- shared helpers ----------------
__device__ __forceinline__ void mma_f16(float& d0, float& d1, float& d2, float& d3,
                                        unsigned a0, unsigned a1, unsigned a2, unsigned a3,
                                        unsigned b0, unsigned b1)
{
    asm volatile(
        "mma.sync.aligned.m16n8k16.row.col.f32.f16.f16.f32 "
        "{%0,%1,%2,%3}, {%4,%5,%6,%7}, {%8,%9}, {%0,%1,%2,%3};"
        : "+f"(d0), "+f"(d1), "+f"(d2), "+f"(d3)
        : "r"(a0), "r"(a1), "r"(a2), "r"(a3), "r"(b0), "r"(b1));
}

__device__ __forceinline__ unsigned pack2(float lo, float hi)
{
    __half2 h = __floats2half2_rn(lo, hi);
    return *reinterpret_cast<unsigned*>(&h);
}

__device__ __forceinline__ int sw2(int k2, int x)
{
    return k2 * 136 + ((k2 >> 2) & 1) * 8 + x;
}

#define STG2_WORDS 1088

// ============================================================================
// GEMM1: C_fp16[M,N] = A_fp32[M,K] * B_fp32[N,K]^T
// ============================================================================
__global__ void __launch_bounds__(256, 2)
gemm_f16_c16(const float* __restrict__ A, const float* __restrict__ B,
             __half* __restrict__ C, int M, int N, int K)
{
    __shared__ unsigned smA[2][STG2_WORDS];
    __shared__ unsigned smB[2][STG2_WORDS];

    const int t    = threadIdx.x;
    const int lane = t & 31;
    const int w    = t >> 5;
    const int g    = lane >> 2;
    const int tig  = lane & 3;
    const int wM   = w >> 2;
    const int wN   = w & 3;
    const int m0   = blockIdx.y * 128;
    const int n0   = blockIdx.x * 128;

    const int r  = t >> 2;
    const int kc = (t & 3) * 4;
    const int k2c = kc >> 1;

    const float* pA0 = A + (size_t)(m0 + r)      * K + kc;
    const float* pA1 = A + (size_t)(m0 + r + 64) * K + kc;
    const float* pB0 = B + (size_t)(n0 + r)      * K + kc;
    const float* pB1 = B + (size_t)(n0 + r + 64) * K + kc;

    float acc[4][4][4] = {};
    const int T = K / 16;

    {
        float4 va0 = *(const float4*)pA0;
        float4 va1 = *(const float4*)pA1;
        float4 vb0 = *(const float4*)pB0;
        float4 vb1 = *(const float4*)pB1;
        smA[0][sw2(k2c,     r)]      = pack2(va0.x, va0.y);
        smA[0][sw2(k2c + 1, r)]      = pack2(va0.z, va0.w);
        smA[0][sw2(k2c,     r + 64)] = pack2(va1.x, va1.y);
        smA[0][sw2(k2c + 1, r + 64)] = pack2(va1.z, va1.w);
        smB[0][sw2(k2c,     r)]      = pack2(vb0.x, vb0.y);
        smB[0][sw2(k2c + 1, r)]      = pack2(vb0.z, vb0.w);
        smB[0][sw2(k2c,     r + 64)] = pack2(vb1.x, vb1.y);
        smB[0][sw2(k2c + 1, r + 64)] = pack2(vb1.z, vb1.w);
    }
    __syncthreads();

    int buf = 0;
    for (int it = 0; it < T; ++it) {
        float4 va0, va1, vb0, vb1;
        const bool more = (it + 1) < T;
        if (more) {
            const int ko = (it + 1) * 16;
            va0 = *(const float4*)(pA0 + ko);
            va1 = *(const float4*)(pA1 + ko);
            vb0 = *(const float4*)(pB0 + ko);
            vb1 = *(const float4*)(pB1 + ko);
        }

        const unsigned* sA = smA[buf];
        const unsigned* sB = smB[buf];
        {
            unsigned af[4][4];
            unsigned bfr[4][2];
#pragma unroll
            for (int ti = 0; ti < 4; ++ti) {
                const int m = wM * 64 + ti * 16 + g;
                af[ti][0] = sA[sw2(tig,     m)];
                af[ti][1] = sA[sw2(tig,     m + 8)];
                af[ti][2] = sA[sw2(tig + 4, m)];
                af[ti][3] = sA[sw2(tig + 4, m + 8)];
            }
#pragma unroll
            for (int tj = 0; tj < 4; ++tj) {
                const int n = wN * 32 + tj * 8 + g;
                bfr[tj][0] = sB[sw2(tig,     n)];
                bfr[tj][1] = sB[sw2(tig + 4, n)];
            }
#pragma unroll
            for (int ti = 0; ti < 4; ++ti)
#pragma unroll
                for (int tj = 0; tj < 4; ++tj)
                    mma_f16(acc[ti][tj][0], acc[ti][tj][1], acc[ti][tj][2], acc[ti][tj][3],
                            af[ti][0], af[ti][1], af[ti][2], af[ti][3],
                            bfr[tj][0], bfr[tj][1]);
        }

        if (more) {
            const int nb = buf ^ 1;
            smA[nb][sw2(k2c,     r)]      = pack2(va0.x, va0.y);
            smA[nb][sw2(k2c + 1, r)]      = pack2(va0.z, va0.w);
            smA[nb][sw2(k2c,     r + 64)] = pack2(va1.x, va1.y);
            smA[nb][sw2(k2c + 1, r + 64)] = pack2(va1.z, va1.w);
            smB[nb][sw2(k2c,     r)]      = pack2(vb0.x, vb0.y);
            smB[nb][sw2(k2c + 1, r)]      = pack2(vb0.z, vb0.w);
            smB[nb][sw2(k2c,     r + 64)] = pack2(vb1.x, vb1.y);
            smB[nb][sw2(k2c + 1, r + 64)] = pack2(vb1.z, vb1.w);
        }
        __syncthreads();
        buf ^= 1;
    }

#pragma unroll
    for (int ti = 0; ti < 4; ++ti) {
#pragma unroll
        for (int tj = 0; tj < 4; ++tj) {
            const int row = m0 + wM * 64 + ti * 16 + g;
            const int col = n0 + wN * 32 + tj * 8 + 2 * tig;
            *(unsigned*)&C[(size_t)row * N + col]       = pack2(acc[ti][tj][0], acc[ti][tj][1]);
            *(unsigned*)&C[(size_t)(row + 8) * N + col] = pack2(acc[ti][tj][2], acc[ti][tj][3]);
        }
    }
}

// ============================================================================
// GEMM2: C_fp32[M,N] = A_fp16[M,K] * B_fp32[N,K]^T   (A loaded with NO convert)
// ============================================================================
__global__ void __launch_bounds__(256, 2)
gemm_a16(const __half* __restrict__ A, const float* __restrict__ B,
         float* __restrict__ C, int M, int N, int K)
{
    __shared__ unsigned smA[2][STG2_WORDS];
    __shared__ unsigned smB[2][STG2_WORDS];

    const int t    = threadIdx.x;
    const int lane = t & 31;
    const int w    = t >> 5;
    const int g    = lane >> 2;
    const int tig  = lane & 3;
    const int wM   = w >> 2;
    const int wN   = w & 3;
    const int m0   = blockIdx.y * 128;
    const int n0   = blockIdx.x * 128;

    const int r  = t >> 2;
    const int kc = (t & 3) * 4;
    const int k2c = kc >> 1;

    const __half* pA0 = A + (size_t)(m0 + r)      * K + kc;
    const __half* pA1 = A + (size_t)(m0 + r + 64) * K + kc;
    const float*  pB0 = B + (size_t)(n0 + r)      * K + kc;
    const float*  pB1 = B + (size_t)(n0 + r + 64) * K + kc;

    float acc[4][4][4] = {};
    const int T = K / 16;

    {
        uint2  ua0 = *(const uint2*)pA0;
        uint2  ua1 = *(const uint2*)pA1;
        float4 vb0 = *(const float4*)pB0;
        float4 vb1 = *(const float4*)pB1;
        smA[0][sw2(k2c,     r)]      = ua0.x;
        smA[0][sw2(k2c + 1, r)]      = ua0.y;
        smA[0][sw2(k2c,     r + 64)] = ua1.x;
        smA[0][sw2(k2c + 1, r + 64)] = ua1.y;
        smB[0][sw2(k2c,     r)]      = pack2(vb0.x, vb0.y);
        smB[0][sw2(k2c + 1, r)]      = pack2(vb0.z, vb0.w);
        smB[0][sw2(k2c,     r + 64)] = pack2(vb1.x, vb1.y);
        smB[0][sw2(k2c + 1, r + 64)] = pack2(vb1.z, vb1.w);
    }
    __syncthreads();

    int buf = 0;
    for (int it = 0; it < T; ++it) {
        uint2 ua0, ua1; float4 vb0, vb1;
        const bool more = (it + 1) < T;
        if (more) {
            const int ko = (it + 1) * 16;
            ua0 = *(const uint2*)(pA0 + ko);
            ua1 = *(const uint2*)(pA1 + ko);
            vb0 = *(const float4*)(pB0 + ko);
            vb1 = *(const float4*)(pB1 + ko);
        }

        const unsigned* sA = smA[buf];
        const unsigned* sB = smB[buf];
        {
            unsigned af[4][4];
            unsigned bfr[4][2];
#pragma unroll
            for (int ti = 0; ti < 4; ++ti) {
                const int m = wM * 64 + ti * 16 + g;
                af[ti][0] = sA[sw2(tig,     m)];
                af[ti][1] = sA[sw2(tig,     m + 8)];
                af[ti][2] = sA[sw2(tig + 4, m)];
                af[ti][3] = sA[sw2(tig + 4, m + 8)];
            }
#pragma unroll
            for (int tj = 0; tj < 4; ++tj) {
                const int n = wN * 32 + tj * 8 + g;
                bfr[tj][0] = sB[sw2(tig,     n)];
                bfr[tj][1] = sB[sw2(tig + 4, n)];
            }
#pragma unroll
            for (int ti = 0; ti < 4; ++ti)
#pragma unroll
                for (int tj = 0; tj < 4; ++tj)
                    mma_f16(acc[ti][tj][0], acc[ti][tj][1], acc[ti][tj][2], acc[ti][tj][3],
                            af[ti][0], af[ti][1], af[ti][2], af[ti][3],
                            bfr[tj][0], bfr[tj][1]);
        }

        if (more) {
            const int nb = buf ^ 1;
            smA[nb][sw2(k2c,     r)]      = ua0.x;
            smA[nb][sw2(k2c + 1, r)]      = ua0.y;
            smA[nb][sw2(k2c,     r + 64)] = ua1.x;
            smA[nb][sw2(k2c + 1, r + 64)] = ua1.y;
            smB[nb][sw2(k2c,     r)]      = pack2(vb0.x, vb0.y);
            smB[nb][sw2(k2c + 1, r)]      = pack2(vb0.z, vb0.w);
            smB[nb][sw2(k2c,     r + 64)] = pack2(vb1.x, vb1.y);
            smB[nb][sw2(k2c + 1, r + 64)] = pack2(vb1.z, vb1.w);
        }
        __syncthreads();
        buf ^= 1;
    }

#pragma unroll
    for (int ti = 0; ti < 4; ++ti) {
#pragma unroll
        for (int tj = 0; tj < 4; ++tj) {
            const int row = m0 + wM * 64 + ti * 16 + g;
            const int col = n0 + wN * 32 + tj * 8 + 2 * tig;
            float2 lo = {acc[ti][tj][0], acc[ti][tj][1]};
            float2 hi = {acc[ti][tj][2], acc[ti][tj][3]};
            *(float2*)&C[(size_t)row * N + col]       = lo;
            *(float2*)&C[(size_t)(row + 8) * N + col] = hi;
        }
    }
}

// ---------------- bias expansion: bias_full[h,i,j] = bias_table[h, idxs[i,j]] ----
__global__ void bias_expand(const float* __restrict__ bias_table,
                            const int*   __restrict__ idxs)
{
    const int i = blockIdx.x * 512 + threadIdx.x;
    if (i >= NHEAD * NTOK * NTOK) return;
    const int h  = i / (NTOK * NTOK);
    const int rc = i - h * NTOK * NTOK;
    g_bias[i] = bias_table[h * NTOK + idxs[rc]];
}

// ---------------- BN stats over fp16 tensor ------------------------------------
__global__ void stats_partial_h(const __half* __restrict__ X, int C)
{
    const int c  = blockIdx.x * 128 + threadIdx.x;
    const int r0 = blockIdx.y * 784;
    float s = 0.f, q = 0.f;
    const __half* p = X + (size_t)r0 * C + c;
    for (int r = 0; r < 784; ++r) {
        const float v = __half2float(p[(size_t)r * C]);
        s += v;
        q += v * v;
    }
    g_psum[blockIdx.y * C + c] = s;
    g_psq [blockIdx.y * C + c] = q;
}

// ---------------- BN stats over fp32 tensor ------------------------------------
__global__ void stats_partial(const float* __restrict__ X, int C)
{
    const int c  = blockIdx.x * 128 + threadIdx.x;
    const int r0 = blockIdx.y * 784;
    float s = 0.f, q = 0.f;
    const float* p = X + (size_t)r0 * C + c;
    for (int r = 0; r < 784; ++r) {
        float v = p[(size_t)r * C];
        s += v;
        q += v * v;
    }
    g_psum[blockIdx.y * C + c] = s;
    g_psq [blockIdx.y * C + c] = q;
}

__global__ void stats_finalize(const float* __restrict__ gam, const float* __restrict__ bet,
                               int C, int which)
{
    const int c = blockIdx.x * blockDim.x + threadIdx.x;
    if (c >= C) return;
    float s = 0.f, q = 0.f;
    for (int i = 0; i < 64; ++i) { s += g_psum[i * C + c]; q += g_psq[i * C + c]; }
    const float invM = 1.0f / (float)MROWS;
    const float mu   = s * invM;
    const float var  = q * invM - mu * mu;
    const float a    = gam[c] * rsqrtf(var + EPSV);
    const float bb   = bet[c] - mu * a;
    if (which == 0) { g_A1[c] = a; g_B1[c] = bb; }
    else            { g_A2[c] = a; g_B2[c] = bb; }
}

// ============================================================================
// Tensor-core attention: one block per (batch, head); 512 threads, 16 warps.
// Reads fp16 Y, writes fp16 O. smem layout unchanged from R16 (172 KB).
// ============================================================================

#define AOFF_Q   0
#define AOFF_K   4160
#define AOFF_V   8320
#define AOFF_S   22144
#define AOFF_P   35712
#define AOFF_A   42624
#define AOFF_B   42816
#define AOFF_INV 43008
#define AOFF_TOT 43072

__device__ __forceinline__ float hswish(float x)
{
    return x * __saturatef((x + 3.0f) * (1.0f / 6.0f));
}

__global__ void __launch_bounds__(512, 1)
attn_kernel()
{
    extern __shared__ float sm[];
    unsigned* usm  = reinterpret_cast<unsigned*>(sm);
    unsigned* uQ   = usm + AOFF_Q;
    unsigned* uK   = usm + AOFF_K;
    unsigned* uV   = usm + AOFF_V;
    float*    S    = sm  + AOFF_S;
    unsigned* uP   = usm + AOFF_P;
    float*    sA   = sm  + AOFF_A;
    float*    sB   = sm  + AOFF_B;
    float*    sInv = sm  + AOFF_INV;

    const int b    = blockIdx.x;
    const int h    = blockIdx.y;
    const int tid  = threadIdx.x;            // 512
    const int w    = tid >> 5;               // 0..15
    const int lane = tid & 31;
    const int g    = lane >> 2;              // 0..7
    const int tig  = lane & 3;               // 0..3

    if (tid < HPC) { sA[tid] = g_A1[h * HPC + tid]; sB[tid] = g_B1[h * HPC + tid]; }

    // zero pads: Q/K rows 196..207, V token cols 196..215, P pad cols 98..107
    for (int i = tid; i < 12 * 20; i += 512) {
        const int rr = 196 + i / 20, cc = i % 20;
        uQ[rr * 20 + cc] = 0;
        uK[rr * 20 + cc] = 0;
    }
    for (int i = tid; i < 128 * 10; i += 512)
        uV[(i / 10) * 108 + 98 + (i % 10)] = 0;
    for (int i = tid; i < 64 * 10; i += 512)
        uP[(i / 10) * 108 + 98 + (i % 10)] = 0;
    __syncthreads();

    // ---- load fp16 Y + BN-normalize + repack fp16 ----
    const size_t base = (size_t)(b * NTOK) * HIDC + h * HPC;
    for (int i = tid; i < NTOK * (HPC / 4); i += 512) {
        const int n  = i / (HPC / 4);
        const int c4 = (i - n * (HPC / 4)) * 4;
        const uint2 raw = *(const uint2*)&g_Yh[base + (size_t)n * HIDC + c4];
        const float2 lo = __half22float2(*reinterpret_cast<const __half2*>(&raw.x));
        const float2 hi = __half22float2(*reinterpret_cast<const __half2*>(&raw.y));
        const float4 a  = *(const float4*)&sA[c4];
        const float4 bb = *(const float4*)&sB[c4];
        float4 y;
        y.x = fmaf(lo.x, a.x, bb.x);
        y.y = fmaf(lo.y, a.y, bb.y);
        y.z = fmaf(hi.x, a.z, bb.z);
        y.w = fmaf(hi.y, a.w, bb.w);
        if (c4 < KDIM) {
            uQ[n * 20 + c4 / 2]     = pack2(y.x, y.y);
            uQ[n * 20 + c4 / 2 + 1] = pack2(y.z, y.w);
        } else if (c4 < 2 * KDIM) {
            const int cc = c4 - KDIM;
            uK[n * 20 + cc / 2]     = pack2(y.x, y.y);
            uK[n * 20 + cc / 2 + 1] = pack2(y.z, y.w);
        } else {
            const int ch = c4 - 2 * KDIM;
            __half* hv = reinterpret_cast<__half*>(uV);
            hv[(ch + 0) * 216 + n] = __float2half(y.x);
            hv[(ch + 1) * 216 + n] = __float2half(y.y);
            hv[(ch + 2) * 216 + n] = __float2half(y.z);
            hv[(ch + 3) * 216 + n] = __float2half(y.w);
        }
    }
    __syncthreads();

    const int rb = w >> 2;           // 0..3: 16-row block within 64-row tile
    const int ws = w & 3;            // 0..3: work split within phase
    const int r0 = rb * 16;

    const float* biasH = g_bias + (size_t)h * NTOK * NTOK;

    for (int tbase = 0; tbase < NTOK; tbase += 64) {
        const int tcount = (NTOK - tbase < 64) ? (NTOK - tbase) : 64;

        // ---- QK^T + scale + bias -> S (fp32) ----
        if (r0 < tcount) {
            const int rowg = tbase + r0 + g;
            unsigned aq0 = uQ[rowg * 20 + tig];
            unsigned aq1 = uQ[(rowg + 8) * 20 + tig];
            unsigned aq2 = uQ[rowg * 20 + tig + 4];
            unsigned aq3 = uQ[(rowg + 8) * 20 + tig + 4];
            unsigned aq4 = uQ[rowg * 20 + 8 + tig];
            unsigned aq5 = uQ[(rowg + 8) * 20 + 8 + tig];
            unsigned aq6 = uQ[rowg * 20 + 8 + tig + 4];
            unsigned aq7 = uQ[(rowg + 8) * 20 + 8 + tig + 4];

            const int rA = r0 + g, rB = r0 + g + 8;
            const float* bRA = biasH + (size_t)(tbase + rA) * NTOK;
            const float* bRB = biasH + (size_t)(tbase + rB) * NTOK;
            for (int j = ws; j < 26; j += 4) {
                const int tok = 8 * j + g;
                const unsigned b00 = uK[tok * 20 + tig];
                const unsigned b01 = uK[tok * 20 + tig + 4];
                const unsigned b10 = uK[tok * 20 + 8 + tig];
                const unsigned b11 = uK[tok * 20 + 8 + tig + 4];
                float c0 = 0.f, c1 = 0.f, c2 = 0.f, c3 = 0.f;
                mma_f16(c0, c1, c2, c3, aq0, aq1, aq2, aq3, b00, b01);
                mma_f16(c0, c1, c2, c3, aq4, aq5, aq6, aq7, b10, b11);
                const int col0 = 8 * j + 2 * tig;
                if (col0 < NTOK) {
                    if (rA < tcount) {
                        const float2 bv = *(const float2*)&bRA[col0];
                        float2 sv = {fmaf(c0, SCALEV, bv.x), fmaf(c1, SCALEV, bv.y)};
                        *(float2*)&S[rA * 212 + col0] = sv;
                    }
                    if (rB < tcount) {
                        const float2 bv = *(const float2*)&bRB[col0];
                        float2 sv = {fmaf(c2, SCALEV, bv.x), fmaf(c3, SCALEV, bv.y)};
                        *(float2*)&S[rB * 212 + col0] = sv;
                    }
                }
            }
        }
        __syncthreads();

        // ---- softmax rows: vectorized, P holds UNNORMALIZED exp ----
        for (int rl = w; rl < tcount; rl += 16) {
            const float4* Sp4 = (const float4*)(S + rl * 212);
            float m = -1e30f;
            for (int j4 = lane; j4 < 49; j4 += 32) {
                const float4 v = Sp4[j4];
                m = fmaxf(m, fmaxf(fmaxf(v.x, v.y), fmaxf(v.z, v.w)));
            }
#pragma unroll
            for (int o = 16; o; o >>= 1) m = fmaxf(m, __shfl_xor_sync(0xffffffffu, m, o));
            float sum = 0.f;
            for (int j4 = lane; j4 < 49; j4 += 32) {
                const float4 v = Sp4[j4];
                const float e0 = __expf(v.x - m);
                const float e1 = __expf(v.y - m);
                const float e2 = __expf(v.z - m);
                const float e3 = __expf(v.w - m);
                sum += (e0 + e1) + (e2 + e3);
                uint2 pk = {pack2(e0, e1), pack2(e2, e3)};
                *(uint2*)&uP[rl * 108 + 2 * j4] = pk;
            }
#pragma unroll
            for (int o = 16; o; o >>= 1) sum += __shfl_xor_sync(0xffffffffu, sum, o);
            if (lane == 0) sInv[rl] = 1.0f / sum;
        }
        __syncthreads();

        // ---- PV (fp16 mma) + deferred normalization + hswish -> g_Oh ----
        if (r0 < tcount) {
            float acc[4][4] = {};
#pragma unroll
            for (int ks = 0; ks < 13; ++ks) {
                const int ko = 8 * ks;
                const unsigned pa0 = uP[(r0 + g) * 108 + ko + tig];
                const unsigned pa1 = uP[(r0 + g + 8) * 108 + ko + tig];
                const unsigned pa2 = uP[(r0 + g) * 108 + ko + tig + 4];
                const unsigned pa3 = uP[(r0 + g + 8) * 108 + ko + tig + 4];
#pragma unroll
                for (int nj = 0; nj < 4; ++nj) {
                    const int ch = ws * 32 + 8 * nj + g;
                    const unsigned vb0 = uV[ch * 108 + ko + tig];
                    const unsigned vb1 = uV[ch * 108 + ko + tig + 4];
                    mma_f16(acc[nj][0], acc[nj][1], acc[nj][2], acc[nj][3],
                            pa0, pa1, pa2, pa3, vb0, vb1);
                }
            }
            const int rA = r0 + g, rB = r0 + g + 8;
            const float invA = (rA < tcount) ? sInv[rA] : 0.f;
            const float invB = (rB < tcount) ? sInv[rB] : 0.f;
#pragma unroll
            for (int nj = 0; nj < 4; ++nj) {
                const int col = h * VDIM + ws * 32 + 8 * nj + 2 * tig;
                if (rA < tcount) {
                    *(unsigned*)&g_Oh[(size_t)(b * NTOK + tbase + rA) * DHC + col] =
                        pack2(hswish(acc[nj][0] * invA), hswish(acc[nj][1] * invA));
                }
                if (rB < tcount) {
                    *(unsigned*)&g_Oh[(size_t)(b * NTOK + tbase + rB) * DHC + col] =
                        pack2(hswish(acc[nj][2] * invB), hswish(acc[nj][3] * invB));
                }
            }
        }
        __syncthreads();
    }
}

// ---------------- final BN apply (in place on d_out) ----------------------------
__global__ void norm2_kernel(float* __restrict__ Z)
{
    const size_t i = (size_t)blockIdx.x * 256 + threadIdx.x;
    float4 z = ((float4*)Z)[i];
    const int c4 = (int)(i & (DIMC / 4 - 1));
    const float4 a  = ((const float4*)g_A2)[c4];
    const float4 bb = ((const float4*)g_B2)[c4];
    z.x = fmaf(z.x, a.x, bb.x);
    z.y = fmaf(z.y, a.y, bb.y);
    z.z = fmaf(z.z, a.z, bb.z);
    z.w = fmaf(z.w, a.w, bb.w);
    ((float4*)Z)[i] = z;
}

// ---------------- launch ---------------------------------------------------------
extern "C" void kernel_launch(void* const* d_in, const int* in_sizes, int n_in,
                              void* d_out, int out_size)
{
    const float* x          = (const float*)d_in[0];
    const float* Wqkv       = (const float*)d_in[1];
    const float* g1         = (const float*)d_in[2];
    const float* b1         = (const float*)d_in[3];
    const float* bias_table = (const float*)d_in[4];
    const float* Wproj      = (const float*)d_in[5];
    const float* g2         = (const float*)d_in[6];
    const float* b2         = (const float*)d_in[7];
    const int*   idxs       = (const int*)d_in[8];
    float*       out        = (float*)d_out;

    __half *Y, *O;
    cudaGetSymbolAddress((void**)&Y, g_Yh);
    cudaGetSymbolAddress((void**)&O, g_Oh);

    const size_t attn_smem = (size_t)AOFF_TOT * sizeof(float);
    cudaFuncSetAttribute(attn_kernel, cudaFuncAttributeMaxDynamicSharedMemorySize,
                         (int)attn_smem);

    // 0) expand relative-position bias to full [H,N,N] (L2-resident)
    bias_expand<<<(NHEAD * NTOK * NTOK + 511) / 512, 512>>>(bias_table, idxs);
    // 1) h = x @ Wqkv^T  -> fp16
    gemm_f16_c16<<<dim3(HIDC / 128, MROWS / 128), 256>>>(x, Wqkv, Y, MROWS, HIDC, DIMC);
    // 2) BN1 stats -> affine  (fp16 reads)
    stats_partial_h<<<dim3(HIDC / 128, 64), 128>>>(Y, HIDC);
    stats_finalize<<<6, 256>>>(g1, b1, HIDC, 0);
    // 3) attention + hardswish (fp16 in, fp16 out)
    attn_kernel<<<dim3(BATCHN, NHEAD), 512, attn_smem>>>();
    // 4) Z = o @ Wproj^T  (fp16 A direct, into fp32 d_out)
    gemm_a16<<<dim3(DIMC / 128, MROWS / 128), 256>>>(O, Wproj, out, MROWS, DIMC, DHC);
    // 5) BN2 stats -> affine
    stats_partial<<<dim3(DIMC / 128, 64), 128>>>(out, DIMC);
    stats_finalize<<<1, 256>>>(g2, b2, DIMC, 1);
    // 6) apply BN2 in place
    norm2_kernel<<<(MROWS * DIMC / 4) / 256, 256>>>(out);
}